// round 15
// baseline (speedup 1.0000x reference)
#include <cuda_runtime.h>
#include <cuda_bf16.h>

#define BB 4
#define FF 9976
#define FPAD 9984
#define NV 5023
#define HH 224
#define WW 224
#define NPIX (HH*WW)
#define EPSR 1e-8f
#define BIGD 1000000.0f
#define CHT 128               // triangles per smem chunk
#define QNAN __int_as_float(0x7fc00000)
#define INV224 (1.0f / 224.0f)   // rn(1/224): algsimp divide->recip-mul (eager op)

// Per-triangle setup: 3 float4 per triangle
//  T[0] = {dy12, dx21, dy20, dx02}
//  T[1] = {x2,   y2,   inv_den, 0}   (inv_den = NaN if degenerate/padding)
//  T[2] = {iz0,  iz1,  iz2,  0}
static __device__ float4 g_T[BB * FPAD * 3];

// EAGER transform (CONFIRMED direction by R3/R10/R13): plain two-rounding
// mul/add, /224 as standalone multiply by rn(1/224), -1 add separate & plain.
__device__ __forceinline__ float xform_xy(float v) {
    float s = __fadd_rn(__fmul_rn(-v, 112.0f), 112.0f);
    s = __fadd_rn(223.0f, -s);
    float t = __fadd_rn(__fmul_rn(2.0f, s), 1.0f);
    t = __fmul_rn(t, INV224);                              // recip-mul
    s = __fadd_rn(-1.0f, t);
    s = __fadd_rn(__fmul_rn(s, 112.0f), 112.0f);
    return s;
}

__global__ void setup_kernel(const float* __restrict__ verts,
                             const int*   __restrict__ faces) {
    int i = blockIdx.x * blockDim.x + threadIdx.x;
    if (i >= BB * FPAD) return;
    int b = i / FPAD;
    int f = i - b * FPAD;

    float4 A, Bv, C;
    if (f >= FF) {
        A  = make_float4(0.f, 0.f, 0.f, 0.f);
        Bv = make_float4(0.f, 0.f, QNAN, 0.f);
        C  = make_float4(0.f, 0.f, 0.f, 0.f);
    } else {
        const int* fp = faces + ((size_t)b * FF + f) * 3;
        float xs[3], ys[3], zs[3];
        #pragma unroll
        for (int k = 0; k < 3; k++) {
            int vi = fp[k];
            const float* vp = verts + ((size_t)b * NV + vi) * 3;
            xs[k] = xform_xy(vp[0]);
            ys[k] = xform_xy(vp[1]);
            zs[k] = __fmul_rn(vp[2], 112.0f);   // rn(224z)/2 == rn(112z) exactly
        }
        float dy12 = ys[1] - ys[2];
        float dx21 = xs[2] - xs[1];
        float dy20 = ys[2] - ys[0];
        float dx02 = xs[0] - xs[2];
        float dy02 = ys[0] - ys[2];
        // fused (single-use muls, first product): confirmed helpful R3->R13
        float denom = __fmaf_rn(dy12, dx02, __fmul_rn(dx21, dy02));
        float inv_den = (fabsf(denom) > EPSR) ? __fdiv_rn(1.0f, denom) : QNAN;
        float iz0 = __fdiv_rn(1.0f, (fabsf(zs[0]) > EPSR) ? zs[0] : 1.0f);
        float iz1 = __fdiv_rn(1.0f, (fabsf(zs[1]) > EPSR) ? zs[1] : 1.0f);
        float iz2 = __fdiv_rn(1.0f, (fabsf(zs[2]) > EPSR) ? zs[2] : 1.0f);
        A  = make_float4(dy12, dx21, dy20, dx02);
        Bv = make_float4(xs[2], ys[2], inv_den, 0.f);
        C  = make_float4(iz0, iz1, iz2, 0.f);
    }
    float4* t = g_T + (size_t)i * 3;
    t[0] = A; t[1] = Bv; t[2] = C;
}

// Body shapes (this round):
//  n0/n1 : fma(dyXX, dxp, mul(dxXX, dyp))   [confirmed]
//  w0/w1 : plain muls
//  w2    : plain (1 - w0) - w1              [confirmed: fused w2 hurt in R10]
//  invd  : FUSED fma(w2,iz2, fma(w0,iz0, mul(w1,iz1)))  <-- the changed bit
//  bary_k: mul(mul(w_k, iz_k), dep)
struct TriEval {
    float w0, w1, w2, dep;
    bool inside;
};

__device__ __forceinline__ TriEval eval_tri(float4 A, float4 Bv, float4 C,
                                            float pxf, float pyf) {
    TriEval r;
    float dxp = pxf - Bv.x;
    float dyp = pyf - Bv.y;
    float id  = Bv.z;
    float n0 = __fmaf_rn(A.x, dxp, __fmul_rn(A.y, dyp));
    float n1 = __fmaf_rn(A.z, dxp, __fmul_rn(A.w, dyp));
    r.w0 = __fmul_rn(n0, id);
    r.w1 = __fmul_rn(n1, id);
    r.w2 = __fadd_rn(__fadd_rn(1.0f, -r.w0), -r.w1);   // plain
    r.inside = (r.w0 >= 0.0f) & (r.w1 >= 0.0f) & (r.w2 >= 0.0f);
    float m1 = __fmul_rn(r.w1, C.y);
    float invd = __fmaf_rn(r.w2, C.z, __fmaf_rn(r.w0, C.x, m1));   // FUSED
    r.dep = __fdiv_rn(1.0f, (fabsf(invd) > EPSR) ? invd : 1.0f);
    return r;
}

__global__ __launch_bounds__(256)
void raster_kernel(const float* __restrict__ attrs,
                   float*       __restrict__ out) {
    const int b  = blockIdx.z;
    const int lx = threadIdx.x & 31;
    const int ly = threadIdx.x >> 5;
    const int px = blockIdx.x * 32 + lx;
    const int py = blockIdx.y * 8  + ly;
    const float pxf = (float)px;
    const float pyf = (float)py;

    __shared__ float4 sT[CHT * 3];

    float bestd = BIGD;
    int   besti = -1;

    const float4* gT = g_T + (size_t)b * FPAD * 3;

    for (int base = 0; base < FPAD; base += CHT) {
        __syncthreads();
        for (int i = threadIdx.x; i < CHT * 3; i += 256)
            sT[i] = gT[(size_t)base * 3 + i];
        __syncthreads();

        #pragma unroll 4
        for (int j = 0; j < CHT; ++j) {
            float4 A  = sT[j * 3 + 0];
            float4 Bv = sT[j * 3 + 1];
            float4 C  = sT[j * 3 + 2];
            float dxp = pxf - Bv.x;
            float dyp = pyf - Bv.y;
            float n0 = __fmaf_rn(A.x, dxp, __fmul_rn(A.y, dyp));
            float n1 = __fmaf_rn(A.z, dxp, __fmul_rn(A.w, dyp));
            float w0 = __fmul_rn(n0, Bv.z);
            float w1 = __fmul_rn(n1, Bv.z);
            float w2 = __fadd_rn(__fadd_rn(1.0f, -w0), -w1);   // plain
            bool inside = (w0 >= 0.0f) & (w1 >= 0.0f) & (w2 >= 0.0f);
            if (__any_sync(0xffffffffu, inside)) {
                float m1   = __fmul_rn(w1, C.y);
                float invd = __fmaf_rn(w2, C.z, __fmaf_rn(w0, C.x, m1)); // FUSED
                float dep  = __fdiv_rn(1.0f, (fabsf(invd) > EPSR) ? invd : 1.0f);
                if (inside & (dep < bestd)) { bestd = dep; besti = base + j; }
            }
        }
    }

    // ---- epilogue: recompute winner barycentrics, gather attrs, write 17 ch
    const int oidx = py * WW + px;
    float* outb = out + (size_t)b * 17 * NPIX;

    if (besti < 0) {
        #pragma unroll
        for (int d = 0; d < 17; d++)
            outb[(size_t)d * NPIX + oidx] = 0.0f;
        return;
    }

    float4 A  = gT[(size_t)besti * 3 + 0];
    float4 Bv = gT[(size_t)besti * 3 + 1];
    float4 C  = gT[(size_t)besti * 3 + 2];
    TriEval e = eval_tri(A, Bv, C, pxf, pyf);
    // bary_k = mul(mul(w_k, iz_k), dep)  (dep from FUSED invd)
    float b0 = __fmul_rn(__fmul_rn(e.w0, C.x), e.dep);
    float b1 = __fmul_rn(__fmul_rn(e.w1, C.y), e.dep);
    float b2 = __fmul_rn(__fmul_rn(e.w2, C.z), e.dep);

    const float4* ap = (const float4*)(attrs + ((size_t)b * FF + besti) * 48);
    #pragma unroll
    for (int q = 0; q < 4; q++) {
        float4 v0 = ap[q + 0];
        float4 v1 = ap[q + 4];
        float4 v2 = ap[q + 8];
        float4 pv;
        // ((p0+p1)+p2): inner fma(b0,a0, mul(b1,a1)); outer fma(b2,a2, inner)
        pv.x = __fmaf_rn(b2, v2.x, __fmaf_rn(b0, v0.x, __fmul_rn(b1, v1.x)));
        pv.y = __fmaf_rn(b2, v2.y, __fmaf_rn(b0, v0.y, __fmul_rn(b1, v1.y)));
        pv.z = __fmaf_rn(b2, v2.z, __fmaf_rn(b0, v0.z, __fmul_rn(b1, v1.z)));
        pv.w = __fmaf_rn(b2, v2.w, __fmaf_rn(b0, v0.w, __fmul_rn(b1, v1.w)));
        int d = q * 4;
        outb[(size_t)(d + 0) * NPIX + oidx] = pv.x;
        outb[(size_t)(d + 1) * NPIX + oidx] = pv.y;
        outb[(size_t)(d + 2) * NPIX + oidx] = pv.z;
        outb[(size_t)(d + 3) * NPIX + oidx] = pv.w;
    }
    outb[(size_t)16 * NPIX + oidx] = 1.0f;
}

extern "C" void kernel_launch(void* const* d_in, const int* in_sizes, int n_in,
                              void* d_out, int out_size) {
    // Identify inputs by element count — robust to metadata ordering.
    const float* vertices = nullptr;
    const int*   faces    = nullptr;
    const float* attrs    = nullptr;
    for (int i = 0; i < n_in; i++) {
        if      (in_sizes[i] == 60276)   vertices = (const float*)d_in[i];
        else if (in_sizes[i] == 119712)  faces    = (const int*)  d_in[i];
        else if (in_sizes[i] == 1915392) attrs    = (const float*)d_in[i];
    }
    float* out = (float*)d_out;  // [4,17,224,224] f32

    {
        int n = BB * FPAD;
        setup_kernel<<<(n + 255) / 256, 256>>>(vertices, faces);
    }
    {
        dim3 grid(WW / 32, HH / 8, BB);
        raster_kernel<<<grid, 256>>>(attrs, out);
    }
}